// round 11
// baseline (speedup 1.0000x reference)
#include <cuda_runtime.h>
#include <cuda_bf16.h>
#include <math.h>
#include <stdint.h>

#define N_NODES 20000
#define D_IN    128
#define E_RAW   320000
#define E_TOT   (E_RAW + N_NODES)
#define F1      512
#define F2      64
#define OUTF    32

// ---------------- scratch ----------------------------------------------------
__device__ float g_xl1[(size_t)N_NODES * F1];
__device__ float g_xr1[(size_t)N_NODES * F1];
__device__ float g_xl2[(size_t)N_NODES * F2];
__device__ float g_xr2[(size_t)N_NODES * F2];
__device__ int   g_deg[N_NODES];
__device__ int   g_part[N_NODES];
__device__ int   g_bsum[32];
__device__ int   g_rowptr[N_NODES + 1];
__device__ int   g_cursor[N_NODES];
__device__ int   g_eidx[E_TOT];
// split-bf16 operands
__device__ __nv_bfloat16 g_xh  [(size_t)N_NODES * D_IN];
__device__ __nv_bfloat16 g_xlo [(size_t)N_NODES * D_IN];
__device__ __nv_bfloat16 g_h1h [(size_t)N_NODES * F1];
__device__ __nv_bfloat16 g_h1lo[(size_t)N_NODES * F1];
__device__ __nv_bfloat16 g_w1h [2 * F1 * D_IN];   // [w][n][k]
__device__ __nv_bfloat16 g_w1lo[2 * F1 * D_IN];
__device__ __nv_bfloat16 g_w2h [2 * F2 * F1];     // [w][n][k]
__device__ __nv_bfloat16 g_w2lo[2 * F2 * F1];

__device__ __forceinline__ int e_dst(const int* ei, int e) {
    return (e < E_RAW) ? ei[E_RAW + e] : (e - E_RAW);
}

// ---------------- CSR build --------------------------------------------------
__global__ void count_kernel(const int* __restrict__ ei) {
    int e = blockIdx.x * blockDim.x + threadIdx.x;
    if (e >= E_TOT) return;
    atomicAdd(&g_deg[e_dst(ei, e)], 1);
}

__global__ void scan1_kernel() {
    __shared__ int sh[1024];
    int t = threadIdx.x;
    int i = blockIdx.x * 1024 + t;
    int v = (i < N_NODES) ? g_deg[i] : 0;
    sh[t] = v;
    __syncthreads();
    #pragma unroll
    for (int off = 1; off < 1024; off <<= 1) {
        int u = (t >= off) ? sh[t - off] : 0;
        __syncthreads();
        sh[t] += u;
        __syncthreads();
    }
    if (i < N_NODES) g_part[i] = sh[t];
    if (t == 1023) g_bsum[blockIdx.x] = sh[t];
}
__global__ void scan23_kernel() {
    int i = blockIdx.x * blockDim.x + threadIdx.x;
    if (i >= N_NODES) return;
    int b = i >> 10;
    int boff = 0;
    for (int j = 0; j < b; j++) boff += g_bsum[j];
    int rp = g_part[i] - g_deg[i] + boff;
    g_rowptr[i] = rp;
    g_cursor[i] = rp;
    if (i == N_NODES - 1) g_rowptr[N_NODES] = g_part[i] + boff;
}

__global__ void scatter_kernel(const int* __restrict__ ei) {
    int e = blockIdx.x * blockDim.x + threadIdx.x;
    if (e >= E_TOT) return;
    int d = e_dst(ei, e);
    int pos = atomicAdd(&g_cursor[d], 1);
    g_eidx[pos] = e;
}

// ---------------- fp32 -> split bf16 (hi + lo) --------------------------------
__device__ __forceinline__ void split2(float v, __nv_bfloat16* ph, __nv_bfloat16* pl) {
    __nv_bfloat16 h = __float2bfloat16(v);
    *ph = h;
    *pl = __float2bfloat16(v - __bfloat162float(h));
}
__global__ void split_x_kernel(const float* __restrict__ x) {
    int i = blockIdx.x * blockDim.x + threadIdx.x;
    if (i >= N_NODES * D_IN) return;
    split2(x[i], &g_xh[i], &g_xlo[i]);
}
__global__ void split_w_kernel(const float* __restrict__ W1l, const float* __restrict__ W1r,
                               const float* __restrict__ W2l, const float* __restrict__ W2r) {
    int i = blockIdx.x * blockDim.x + threadIdx.x;
    if (i < F1 * D_IN) {
        int k = i / F1, n = i % F1;
        split2(W1l[i], &g_w1h[n * D_IN + k], &g_w1lo[n * D_IN + k]);
        split2(W1r[i], &g_w1h[F1 * D_IN + n * D_IN + k], &g_w1lo[F1 * D_IN + n * D_IN + k]);
    } else {
        int j = i - F1 * D_IN;
        if (j >= F2 * F1) return;
        int k = j / F2, n = j % F2;
        split2(W2l[j], &g_w2h[n * F1 + k], &g_w2lo[n * F1 + k]);
        split2(W2r[j], &g_w2h[F2 * F1 + n * F1 + k], &g_w2lo[F2 * F1 + n * F1 + k]);
    }
}

// ---------------- split-bf16 GEMM on mma.sync (R8 body) -----------------------
#define SPAD 40

__device__ __forceinline__ uint32_t lds_u32(const __nv_bfloat16* s, int row, int col) {
    return *(const uint32_t*)((const char*)s + row * (SPAD * 2) + col * 2);
}
__device__ __forceinline__ void mma_bf16(float* c, const uint32_t* a, const uint32_t* b) {
    asm volatile(
        "mma.sync.aligned.m16n8k16.row.col.f32.bf16.bf16.f32 "
        "{%0,%1,%2,%3}, {%4,%5,%6,%7}, {%8,%9}, {%0,%1,%2,%3};"
        : "+f"(c[0]), "+f"(c[1]), "+f"(c[2]), "+f"(c[3])
        : "r"(a[0]), "r"(a[1]), "r"(a[2]), "r"(a[3]), "r"(b[0]), "r"(b[1]));
}

__global__ void __launch_bounds__(256) gemm_mma(
    const __nv_bfloat16* __restrict__ Ah, const __nv_bfloat16* __restrict__ Al,
    const __nv_bfloat16* __restrict__ Bh, const __nv_bfloat16* __restrict__ Bl,
    float* __restrict__ C0, float* __restrict__ C1,
    int M, int N, int K, int ntPerW)
{
    __shared__ __nv_bfloat16 sAh[128 * SPAD], sAl[128 * SPAD];
    __shared__ __nv_bfloat16 sBh[64 * SPAD],  sBl[64 * SPAD];

    int tid = threadIdx.x;
    int wid = tid >> 5, lane = tid & 31;
    int w  = blockIdx.x / ntPerW;
    int nt = blockIdx.x % ntPerW;
    int bm = blockIdx.y * 128;

    const __nv_bfloat16* Bth = Bh + (size_t)w * N * K + (size_t)(nt * 64) * K;
    const __nv_bfloat16* Btl = Bl + (size_t)w * N * K + (size_t)(nt * 64) * K;
    float* C = w ? C1 : C0;

    int wm = wid & 3, wn = wid >> 2;
    int g = lane >> 2, t2 = (lane & 3) * 2;

    int ra0 = tid >> 2, qa0 = tid & 3;
    int ra1 = (tid + 256) >> 2, qa1 = (tid + 256) & 3;
    int rb = tid >> 2, qb = tid & 3;

    float acc[2][4][4];
    #pragma unroll
    for (int i = 0; i < 2; i++)
        #pragma unroll
        for (int j = 0; j < 4; j++)
            #pragma unroll
            for (int q = 0; q < 4; q++) acc[i][j][q] = 0.f;

    int nk = K >> 5;
    uint4 pavh0, pavl0, pavh1, pavl1, pbvh, pbvl;
    {
        int gm0 = bm + ra0, gm1 = bm + ra1;
        pavh0 = pavl0 = make_uint4(0,0,0,0);
        pavh1 = pavl1 = make_uint4(0,0,0,0);
        if (gm0 < M) { pavh0 = *(const uint4*)(Ah + (size_t)gm0 * K + qa0 * 8);
                       pavl0 = *(const uint4*)(Al + (size_t)gm0 * K + qa0 * 8); }
        if (gm1 < M) { pavh1 = *(const uint4*)(Ah + (size_t)gm1 * K + qa1 * 8);
                       pavl1 = *(const uint4*)(Al + (size_t)gm1 * K + qa1 * 8); }
        pbvh = *(const uint4*)(Bth + (size_t)rb * K + qb * 8);
        pbvl = *(const uint4*)(Btl + (size_t)rb * K + qb * 8);
    }

    for (int kt = 0; kt < nk; kt++) {
        *(uint4*)((char*)sAh + ra0 * (SPAD * 2) + qa0 * 16) = pavh0;
        *(uint4*)((char*)sAl + ra0 * (SPAD * 2) + qa0 * 16) = pavl0;
        *(uint4*)((char*)sAh + ra1 * (SPAD * 2) + qa1 * 16) = pavh1;
        *(uint4*)((char*)sAl + ra1 * (SPAD * 2) + qa1 * 16) = pavl1;
        *(uint4*)((char*)sBh + rb * (SPAD * 2) + qb * 16) = pbvh;
        *(uint4*)((char*)sBl + rb * (SPAD * 2) + qb * 16) = pbvl;
        __syncthreads();

        if (kt + 1 < nk) {
            int k0 = (kt + 1) << 5;
            int gm0 = bm + ra0, gm1 = bm + ra1;
            if (gm0 < M) { pavh0 = *(const uint4*)(Ah + (size_t)gm0 * K + k0 + qa0 * 8);
                           pavl0 = *(const uint4*)(Al + (size_t)gm0 * K + k0 + qa0 * 8); }
            if (gm1 < M) { pavh1 = *(const uint4*)(Ah + (size_t)gm1 * K + k0 + qa1 * 8);
                           pavl1 = *(const uint4*)(Al + (size_t)gm1 * K + k0 + qa1 * 8); }
            pbvh = *(const uint4*)(Bth + (size_t)rb * K + k0 + qb * 8);
            pbvl = *(const uint4*)(Btl + (size_t)rb * K + k0 + qb * 8);
        }

        #pragma unroll
        for (int kk = 0; kk < 32; kk += 16) {
            uint32_t ah[2][4], al[2][4], bhf[4][2], blf[4][2];
            #pragma unroll
            for (int i = 0; i < 2; i++) {
                int r = wm * 32 + i * 16;
                ah[i][0] = lds_u32(sAh, r + g,     kk + t2);
                ah[i][1] = lds_u32(sAh, r + g + 8, kk + t2);
                ah[i][2] = lds_u32(sAh, r + g,     kk + t2 + 8);
                ah[i][3] = lds_u32(sAh, r + g + 8, kk + t2 + 8);
                al[i][0] = lds_u32(sAl, r + g,     kk + t2);
                al[i][1] = lds_u32(sAl, r + g + 8, kk + t2);
                al[i][2] = lds_u32(sAl, r + g,     kk + t2 + 8);
                al[i][3] = lds_u32(sAl, r + g + 8, kk + t2 + 8);
            }
            #pragma unroll
            for (int j = 0; j < 4; j++) {
                int n = wn * 32 + j * 8 + g;
                bhf[j][0] = lds_u32(sBh, n, kk + t2);
                bhf[j][1] = lds_u32(sBh, n, kk + t2 + 8);
                blf[j][0] = lds_u32(sBl, n, kk + t2);
                blf[j][1] = lds_u32(sBl, n, kk + t2 + 8);
            }
            #pragma unroll
            for (int i = 0; i < 2; i++)
                #pragma unroll
                for (int j = 0; j < 4; j++) {
                    mma_bf16(acc[i][j], ah[i], bhf[j]);
                    mma_bf16(acc[i][j], ah[i], blf[j]);
                    mma_bf16(acc[i][j], al[i], bhf[j]);
                }
        }
        __syncthreads();
    }

    #pragma unroll
    for (int i = 0; i < 2; i++) {
        int r0 = bm + wm * 32 + i * 16 + g;
        #pragma unroll
        for (int j = 0; j < 4; j++) {
            int c = nt * 64 + wn * 32 + j * 8 + t2;
            if (r0 < M)
                *(float2*)(C + (size_t)r0 * N + c) = make_float2(acc[i][j][0], acc[i][j][1]);
            if (r0 + 8 < M)
                *(float2*)(C + (size_t)(r0 + 8) * N + c) = make_float2(acc[i][j][2], acc[i][j][3]);
        }
    }
}

// ---------------- 4-edge softmax-state merge helper ---------------------------
// state: (m, den, acc[8]) per lane; merges across lane groups via xor 8, 16.
__device__ __forceinline__ void merge_states(float& m, float& den, float4& a0, float4& a1) {
    #pragma unroll
    for (int off = 8; off <= 16; off <<= 1) {
        float mo   = __shfl_xor_sync(0xffffffffu, m, off);
        float deno = __shfl_xor_sync(0xffffffffu, den, off);
        float4 b0, b1;
        b0.x = __shfl_xor_sync(0xffffffffu, a0.x, off);
        b0.y = __shfl_xor_sync(0xffffffffu, a0.y, off);
        b0.z = __shfl_xor_sync(0xffffffffu, a0.z, off);
        b0.w = __shfl_xor_sync(0xffffffffu, a0.w, off);
        b1.x = __shfl_xor_sync(0xffffffffu, a1.x, off);
        b1.y = __shfl_xor_sync(0xffffffffu, a1.y, off);
        b1.z = __shfl_xor_sync(0xffffffffu, a1.z, off);
        b1.w = __shfl_xor_sync(0xffffffffu, a1.w, off);
        float M = fmaxf(m, mo);
        float sA = (m  > -INFINITY) ? __expf(m  - M) : 0.f;
        float sB = (mo > -INFINITY) ? __expf(mo - M) : 0.f;
        den = den * sA + deno * sB;
        a0.x = a0.x * sA + b0.x * sB; a0.y = a0.y * sA + b0.y * sB;
        a0.z = a0.z * sA + b0.z * sB; a0.w = a0.w * sA + b0.w * sB;
        a1.x = a1.x * sA + b1.x * sB; a1.y = a1.y * sA + b1.y * sB;
        a1.z = a1.z * sA + b1.z * sB; a1.w = a1.w * sA + b1.w * sB;
        m = M;
    }
}

// ---------------- fused GAT layer 1 (quad-edge: 8 lanes/edge x 8 ch/lane) -----
__global__ void gat1_kernel(const int* __restrict__ ei, const float* __restrict__ att,
                            const float* __restrict__ b1)
{
    int n = blockIdx.x;
    int w = threadIdx.x >> 5, lane = threadIdx.x & 31;
    int gid = lane >> 3, ll = lane & 7;
    int c = w * 64 + ll * 8;   // 8 channels per lane

    const float* xrp = g_xr1 + (size_t)n * F1 + c;
    float4 xr0 = *(const float4*)xrp;
    float4 xr1 = *(const float4*)(xrp + 4);
    float4 at0 = *(const float4*)(att + c);
    float4 at1 = *(const float4*)(att + c + 4);

    int r0 = g_rowptr[n], r1 = g_rowptr[n + 1];
    int nIter = (r1 - r0 + 3) >> 2;
    float m = -INFINITY, den = 0.f;
    float4 a0 = make_float4(0.f,0.f,0.f,0.f), a1 = a0;

    for (int it = 0; it < nIter; it++) {
        int p = r0 + it * 4 + gid;
        bool valid = p < r1;
        int pp = valid ? p : (r1 - 1);
        int e = g_eidx[pp];
        int s = (e < E_RAW) ? ei[e] : (e - E_RAW);
        const float* xlp = g_xl1 + (size_t)s * F1 + c;
        float4 x0 = *(const float4*)xlp;
        float4 x1 = *(const float4*)(xlp + 4);
        float v, sc = 0.f;
        v = x0.x + xr0.x; v = v > 0.f ? v : 0.2f * v; sc += v * at0.x;
        v = x0.y + xr0.y; v = v > 0.f ? v : 0.2f * v; sc += v * at0.y;
        v = x0.z + xr0.z; v = v > 0.f ? v : 0.2f * v; sc += v * at0.z;
        v = x0.w + xr0.w; v = v > 0.f ? v : 0.2f * v; sc += v * at0.w;
        v = x1.x + xr1.x; v = v > 0.f ? v : 0.2f * v; sc += v * at1.x;
        v = x1.y + xr1.y; v = v > 0.f ? v : 0.2f * v; sc += v * at1.y;
        v = x1.z + xr1.z; v = v > 0.f ? v : 0.2f * v; sc += v * at1.z;
        v = x1.w + xr1.w; v = v > 0.f ? v : 0.2f * v; sc += v * at1.w;
        sc += __shfl_xor_sync(0xffffffffu, sc, 1);
        sc += __shfl_xor_sync(0xffffffffu, sc, 2);
        sc += __shfl_xor_sync(0xffffffffu, sc, 4);
        if (valid && sc > m) {
            float r = __expf(m - sc);
            den *= r;
            a0.x *= r; a0.y *= r; a0.z *= r; a0.w *= r;
            a1.x *= r; a1.y *= r; a1.z *= r; a1.w *= r;
            m = sc;
        }
        float a = valid ? __expf(sc - m) : 0.f;
        den += a;
        a0.x += a * x0.x; a0.y += a * x0.y; a0.z += a * x0.z; a0.w += a * x0.w;
        a1.x += a * x1.x; a1.y += a * x1.y; a1.z += a * x1.z; a1.w += a * x1.w;
    }

    merge_states(m, den, a0, a1);

    if (gid == 0) {
        float4 bb0 = *(const float4*)(b1 + c);
        float4 bb1 = *(const float4*)(b1 + c + 4);
        float invd = 1.0f / den;
        float o[8];
        o[0] = a0.x * invd + bb0.x; o[1] = a0.y * invd + bb0.y;
        o[2] = a0.z * invd + bb0.z; o[3] = a0.w * invd + bb0.w;
        o[4] = a1.x * invd + bb1.x; o[5] = a1.y * invd + bb1.y;
        o[6] = a1.z * invd + bb1.z; o[7] = a1.w * invd + bb1.w;
        __nv_bfloat16 h[8], lo[8];
        #pragma unroll
        for (int k = 0; k < 8; k++) {
            float e2 = o[k] > 0.f ? o[k] : __expf(o[k]) - 1.f;
            split2(e2, &h[k], &lo[k]);
        }
        *(uint4*)(g_h1h  + (size_t)n * F1 + c) = *(const uint4*)h;
        *(uint4*)(g_h1lo + (size_t)n * F1 + c) = *(const uint4*)lo;
    }
}

// ---------------- fused GAT layer 2 + linear + elu (quad-edge) ----------------
__global__ void gat2_kernel(const int* __restrict__ ei, const float* __restrict__ att,
                            const float* __restrict__ b2,
                            const float* __restrict__ Wlin, const float* __restrict__ blin,
                            float* __restrict__ out)
{
    __shared__ float sW[64 * 32];
    __shared__ float sb[32];
    __shared__ float sh2[8][64];
    for (int i = threadIdx.x; i < 64 * 32; i += 256) sW[i] = Wlin[i];
    if (threadIdx.x < 32) sb[threadIdx.x] = blin[threadIdx.x];
    __syncthreads();

    int w = threadIdx.x >> 5, lane = threadIdx.x & 31;
    int gid = lane >> 3, ll = lane & 7;
    int n = blockIdx.x * 8 + w;
    int c = ll * 8;

    const float* xrp = g_xr2 + (size_t)n * F2 + c;
    float4 xr0 = *(const float4*)xrp;
    float4 xr1 = *(const float4*)(xrp + 4);
    float4 at0 = *(const float4*)(att + c);
    float4 at1 = *(const float4*)(att + c + 4);

    int r0 = g_rowptr[n], r1 = g_rowptr[n + 1];
    int nIter = (r1 - r0 + 3) >> 2;
    float m = -INFINITY, den = 0.f;
    float4 a0 = make_float4(0.f,0.f,0.f,0.f), a1 = a0;

    for (int it = 0; it < nIter; it++) {
        int p = r0 + it * 4 + gid;
        bool valid = p < r1;
        int pp = valid ? p : (r1 - 1);
        int e = g_eidx[pp];
        int s = (e < E_RAW) ? ei[e] : (e - E_RAW);
        const float* xlp = g_xl2 + (size_t)s * F2 + c;
        float4 x0 = *(const float4*)xlp;
        float4 x1 = *(const float4*)(xlp + 4);
        float v, sc = 0.f;
        v = x0.x + xr0.x; v = v > 0.f ? v : 0.2f * v; sc += v * at0.x;
        v = x0.y + xr0.y; v = v > 0.f ? v : 0.2f * v; sc += v * at0.y;
        v = x0.z + xr0.z; v = v > 0.f ? v : 0.2f * v; sc += v * at0.z;
        v = x0.w + xr0.w; v = v > 0.f ? v : 0.2f * v; sc += v * at0.w;
        v = x1.x + xr1.x; v = v > 0.f ? v : 0.2f * v; sc += v * at1.x;
        v = x1.y + xr1.y; v = v > 0.f ? v : 0.2f * v; sc += v * at1.y;
        v = x1.z + xr1.z; v = v > 0.f ? v : 0.2f * v; sc += v * at1.z;
        v = x1.w + xr1.w; v = v > 0.f ? v : 0.2f * v; sc += v * at1.w;
        sc += __shfl_xor_sync(0xffffffffu, sc, 1);
        sc += __shfl_xor_sync(0xffffffffu, sc, 2);
        sc += __shfl_xor_sync(0xffffffffu, sc, 4);
        if (valid && sc > m) {
            float r = __expf(m - sc);
            den *= r;
            a0.x *= r; a0.y *= r; a0.z *= r; a0.w *= r;
            a1.x *= r; a1.y *= r; a1.z *= r; a1.w *= r;
            m = sc;
        }
        float a = valid ? __expf(sc - m) : 0.f;
        den += a;
        a0.x += a * x0.x; a0.y += a * x0.y; a0.z += a * x0.z; a0.w += a * x0.w;
        a1.x += a * x1.x; a1.y += a * x1.y; a1.z += a * x1.z; a1.w += a * x1.w;
    }

    merge_states(m, den, a0, a1);

    if (gid == 0) {
        float4 bb0 = *(const float4*)(b2 + c);
        float4 bb1 = *(const float4*)(b2 + c + 4);
        float invd = 1.0f / den;
        float o[8];
        o[0] = a0.x * invd + bb0.x; o[1] = a0.y * invd + bb0.y;
        o[2] = a0.z * invd + bb0.z; o[3] = a0.w * invd + bb0.w;
        o[4] = a1.x * invd + bb1.x; o[5] = a1.y * invd + bb1.y;
        o[6] = a1.z * invd + bb1.z; o[7] = a1.w * invd + bb1.w;
        #pragma unroll
        for (int k = 0; k < 8; k++)
            sh2[w][c + k] = o[k] > 0.f ? o[k] : __expf(o[k]) - 1.f;
    }
    __syncwarp();

    float o = sb[lane];
    #pragma unroll
    for (int k = 0; k < 64; k++) o += sh2[w][k] * sW[k * 32 + lane];
    out[(size_t)n * OUTF + lane] = o > 0.f ? o : __expf(o) - 1.f;
}

// ---------------- launch ------------------------------------------------------
extern "C" void kernel_launch(void* const* d_in, const int* in_sizes, int n_in,
                              void* d_out, int out_size) {
    const float* x    = (const float*)d_in[0];
    const int*   ei   = (const int*)  d_in[1];
    const float* W1l  = (const float*)d_in[2];
    const float* W1r  = (const float*)d_in[3];
    const float* att1 = (const float*)d_in[4];
    const float* b1   = (const float*)d_in[5];
    const float* W2l  = (const float*)d_in[6];
    const float* W2r  = (const float*)d_in[7];
    const float* att2 = (const float*)d_in[8];
    const float* b2   = (const float*)d_in[9];
    const float* Wlin = (const float*)d_in[10];
    const float* blin = (const float*)d_in[11];
    float* out = (float*)d_out;

    float *p_xl1, *p_xr1, *p_xl2, *p_xr2;
    int* p_deg;
    __nv_bfloat16 *p_xh, *p_xlo, *p_w1h, *p_w1lo, *p_h1h, *p_h1lo, *p_w2h, *p_w2lo;
    cudaGetSymbolAddress((void**)&p_xl1,  g_xl1);
    cudaGetSymbolAddress((void**)&p_xr1,  g_xr1);
    cudaGetSymbolAddress((void**)&p_xl2,  g_xl2);
    cudaGetSymbolAddress((void**)&p_xr2,  g_xr2);
    cudaGetSymbolAddress((void**)&p_deg,  g_deg);
    cudaGetSymbolAddress((void**)&p_xh,   g_xh);
    cudaGetSymbolAddress((void**)&p_xlo,  g_xlo);
    cudaGetSymbolAddress((void**)&p_w1h,  g_w1h);
    cudaGetSymbolAddress((void**)&p_w1lo, g_w1lo);
    cudaGetSymbolAddress((void**)&p_h1h,  g_h1h);
    cudaGetSymbolAddress((void**)&p_h1lo, g_h1lo);
    cudaGetSymbolAddress((void**)&p_w2h,  g_w2h);
    cudaGetSymbolAddress((void**)&p_w2lo, g_w2lo);

    static cudaStream_t s2 = nullptr;
    static cudaEvent_t evFork = nullptr, evJoin = nullptr;
    if (s2 == nullptr) {
        cudaStreamCreateWithFlags(&s2, cudaStreamNonBlocking);
        cudaEventCreateWithFlags(&evFork, cudaEventDisableTiming);
        cudaEventCreateWithFlags(&evJoin, cudaEventDisableTiming);
    }

    cudaEventRecord(evFork, 0);
    cudaStreamWaitEvent(s2, evFork, 0);

    // --- branch A (s2): CSR build ---
    cudaMemsetAsync(p_deg, 0, N_NODES * sizeof(int), s2);
    count_kernel<<<(E_TOT + 255) / 256, 256, 0, s2>>>(ei);
    int nblk = (N_NODES + 1023) / 1024;
    scan1_kernel<<<nblk, 1024, 0, s2>>>();
    scan23_kernel<<<(N_NODES + 255) / 256, 256, 0, s2>>>();
    scatter_kernel<<<(E_TOT + 255) / 256, 256, 0, s2>>>(ei);
    cudaEventRecord(evJoin, s2);

    // --- branch B (main): splits + layer-1 GEMM ---
    split_x_kernel<<<(N_NODES * D_IN + 255) / 256, 256>>>(x);
    split_w_kernel<<<(F1 * D_IN + F2 * F1 + 255) / 256, 256>>>(W1l, W1r, W2l, W2r);
    gemm_mma<<<dim3(16, (N_NODES + 127) / 128), 256>>>(
        p_xh, p_xlo, p_w1h, p_w1lo, p_xl1, p_xr1, N_NODES, F1, D_IN, 8);

    cudaStreamWaitEvent(0, evJoin, 0);
    gat1_kernel<<<N_NODES, 256>>>(ei, att1, b1);

    gemm_mma<<<dim3(2, (N_NODES + 127) / 128), 256>>>(
        p_h1h, p_h1lo, p_w2h, p_w2lo, p_xl2, p_xr2, N_NODES, F2, F1, 1);
    gat2_kernel<<<N_NODES / 8, 256>>>(ei, att2, b2, Wlin, blin, out);
}

// round 12
// speedup vs baseline: 1.6940x; 1.6940x over previous
#include <cuda_runtime.h>
#include <cuda_bf16.h>
#include <math.h>
#include <stdint.h>

#define N_NODES 20000
#define D_IN    128
#define E_RAW   320000
#define E_TOT   (E_RAW + N_NODES)
#define F1      512
#define F2      64
#define OUTF    32

// ---------------- scratch ----------------------------------------------------
__device__ float g_xl1[(size_t)N_NODES * F1];
__device__ float g_xr1[(size_t)N_NODES * F1];
__device__ float g_xl2[(size_t)N_NODES * F2];
__device__ float g_xr2[(size_t)N_NODES * F2];
__device__ int   g_deg[N_NODES];
__device__ int   g_part[N_NODES];
__device__ int   g_bsum[32];
__device__ int   g_rowptr[N_NODES + 1];
__device__ int   g_cursor[N_NODES];
__device__ int   g_esrc[E_TOT];      // CSR edge list, source node id (pre-resolved)
// split-bf16 operands
__device__ __nv_bfloat16 g_xh  [(size_t)N_NODES * D_IN];
__device__ __nv_bfloat16 g_xlo [(size_t)N_NODES * D_IN];
__device__ __nv_bfloat16 g_h1h [(size_t)N_NODES * F1];
__device__ __nv_bfloat16 g_h1lo[(size_t)N_NODES * F1];
__device__ __nv_bfloat16 g_w1h [2 * F1 * D_IN];   // [w][n][k]
__device__ __nv_bfloat16 g_w1lo[2 * F1 * D_IN];
__device__ __nv_bfloat16 g_w2h [2 * F2 * F1];     // [w][n][k]
__device__ __nv_bfloat16 g_w2lo[2 * F2 * F1];

__device__ __forceinline__ int e_dst(const int* ei, int e) {
    return (e < E_RAW) ? ei[E_RAW + e] : (e - E_RAW);
}

// ---------------- CSR build --------------------------------------------------
__global__ void count_kernel(const int* __restrict__ ei) {
    int e = blockIdx.x * blockDim.x + threadIdx.x;
    if (e >= E_TOT) return;
    atomicAdd(&g_deg[e_dst(ei, e)], 1);
}

__global__ void scan1_kernel() {
    __shared__ int sh[1024];
    int t = threadIdx.x;
    int i = blockIdx.x * 1024 + t;
    int v = (i < N_NODES) ? g_deg[i] : 0;
    sh[t] = v;
    __syncthreads();
    #pragma unroll
    for (int off = 1; off < 1024; off <<= 1) {
        int u = (t >= off) ? sh[t - off] : 0;
        __syncthreads();
        sh[t] += u;
        __syncthreads();
    }
    if (i < N_NODES) g_part[i] = sh[t];
    if (t == 1023) g_bsum[blockIdx.x] = sh[t];
}
__global__ void scan23_kernel() {
    int i = blockIdx.x * blockDim.x + threadIdx.x;
    if (i >= N_NODES) return;
    int b = i >> 10;
    int boff = 0;
    for (int j = 0; j < b; j++) boff += g_bsum[j];
    int rp = g_part[i] - g_deg[i] + boff;
    g_rowptr[i] = rp;
    g_cursor[i] = rp;
    if (i == N_NODES - 1) g_rowptr[N_NODES] = g_part[i] + boff;
}

// scatter stores the RESOLVED source id, removing the ei[e] gather from gat loops
__global__ void scatter_kernel(const int* __restrict__ ei) {
    int e = blockIdx.x * blockDim.x + threadIdx.x;
    if (e >= E_TOT) return;
    int s, d;
    if (e < E_RAW) { s = ei[e]; d = ei[E_RAW + e]; }
    else           { s = e - E_RAW; d = s; }
    int pos = atomicAdd(&g_cursor[d], 1);
    g_esrc[pos] = s;
}

// ---------------- fp32 -> split bf16 (hi + lo) --------------------------------
__device__ __forceinline__ void split2(float v, __nv_bfloat16* ph, __nv_bfloat16* pl) {
    __nv_bfloat16 h = __float2bfloat16(v);
    *ph = h;
    *pl = __float2bfloat16(v - __bfloat162float(h));
}
__global__ void split_x_kernel(const float* __restrict__ x) {
    int i = blockIdx.x * blockDim.x + threadIdx.x;
    if (i >= N_NODES * D_IN) return;
    split2(x[i], &g_xh[i], &g_xlo[i]);
}
__global__ void split_w_kernel(const float* __restrict__ W1l, const float* __restrict__ W1r,
                               const float* __restrict__ W2l, const float* __restrict__ W2r) {
    int i = blockIdx.x * blockDim.x + threadIdx.x;
    if (i < F1 * D_IN) {
        int k = i / F1, n = i % F1;
        split2(W1l[i], &g_w1h[n * D_IN + k], &g_w1lo[n * D_IN + k]);
        split2(W1r[i], &g_w1h[F1 * D_IN + n * D_IN + k], &g_w1lo[F1 * D_IN + n * D_IN + k]);
    } else {
        int j = i - F1 * D_IN;
        if (j >= F2 * F1) return;
        int k = j / F2, n = j % F2;
        split2(W2l[j], &g_w2h[n * F1 + k], &g_w2lo[n * F1 + k]);
        split2(W2r[j], &g_w2h[F2 * F1 + n * F1 + k], &g_w2lo[F2 * F1 + n * F1 + k]);
    }
}

// ---------------- split-bf16 GEMM on mma.sync (R8 body) -----------------------
#define SPAD 40

__device__ __forceinline__ uint32_t lds_u32(const __nv_bfloat16* s, int row, int col) {
    return *(const uint32_t*)((const char*)s + row * (SPAD * 2) + col * 2);
}
__device__ __forceinline__ void mma_bf16(float* c, const uint32_t* a, const uint32_t* b) {
    asm volatile(
        "mma.sync.aligned.m16n8k16.row.col.f32.bf16.bf16.f32 "
        "{%0,%1,%2,%3}, {%4,%5,%6,%7}, {%8,%9}, {%0,%1,%2,%3};"
        : "+f"(c[0]), "+f"(c[1]), "+f"(c[2]), "+f"(c[3])
        : "r"(a[0]), "r"(a[1]), "r"(a[2]), "r"(a[3]), "r"(b[0]), "r"(b[1]));
}

__global__ void __launch_bounds__(256) gemm_mma(
    const __nv_bfloat16* __restrict__ Ah, const __nv_bfloat16* __restrict__ Al,
    const __nv_bfloat16* __restrict__ Bh, const __nv_bfloat16* __restrict__ Bl,
    float* __restrict__ C0, float* __restrict__ C1,
    int M, int N, int K, int ntPerW)
{
    __shared__ __nv_bfloat16 sAh[128 * SPAD], sAl[128 * SPAD];
    __shared__ __nv_bfloat16 sBh[64 * SPAD],  sBl[64 * SPAD];

    int tid = threadIdx.x;
    int wid = tid >> 5, lane = tid & 31;
    int w  = blockIdx.x / ntPerW;
    int nt = blockIdx.x % ntPerW;
    int bm = blockIdx.y * 128;

    const __nv_bfloat16* Bth = Bh + (size_t)w * N * K + (size_t)(nt * 64) * K;
    const __nv_bfloat16* Btl = Bl + (size_t)w * N * K + (size_t)(nt * 64) * K;
    float* C = w ? C1 : C0;

    int wm = wid & 3, wn = wid >> 2;
    int g = lane >> 2, t2 = (lane & 3) * 2;

    int ra0 = tid >> 2, qa0 = tid & 3;
    int ra1 = (tid + 256) >> 2, qa1 = (tid + 256) & 3;
    int rb = tid >> 2, qb = tid & 3;

    float acc[2][4][4];
    #pragma unroll
    for (int i = 0; i < 2; i++)
        #pragma unroll
        for (int j = 0; j < 4; j++)
            #pragma unroll
            for (int q = 0; q < 4; q++) acc[i][j][q] = 0.f;

    int nk = K >> 5;
    uint4 pavh0, pavl0, pavh1, pavl1, pbvh, pbvl;
    {
        int gm0 = bm + ra0, gm1 = bm + ra1;
        pavh0 = pavl0 = make_uint4(0,0,0,0);
        pavh1 = pavl1 = make_uint4(0,0,0,0);
        if (gm0 < M) { pavh0 = *(const uint4*)(Ah + (size_t)gm0 * K + qa0 * 8);
                       pavl0 = *(const uint4*)(Al + (size_t)gm0 * K + qa0 * 8); }
        if (gm1 < M) { pavh1 = *(const uint4*)(Ah + (size_t)gm1 * K + qa1 * 8);
                       pavl1 = *(const uint4*)(Al + (size_t)gm1 * K + qa1 * 8); }
        pbvh = *(const uint4*)(Bth + (size_t)rb * K + qb * 8);
        pbvl = *(const uint4*)(Btl + (size_t)rb * K + qb * 8);
    }

    for (int kt = 0; kt < nk; kt++) {
        *(uint4*)((char*)sAh + ra0 * (SPAD * 2) + qa0 * 16) = pavh0;
        *(uint4*)((char*)sAl + ra0 * (SPAD * 2) + qa0 * 16) = pavl0;
        *(uint4*)((char*)sAh + ra1 * (SPAD * 2) + qa1 * 16) = pavh1;
        *(uint4*)((char*)sAl + ra1 * (SPAD * 2) + qa1 * 16) = pavl1;
        *(uint4*)((char*)sBh + rb * (SPAD * 2) + qb * 16) = pbvh;
        *(uint4*)((char*)sBl + rb * (SPAD * 2) + qb * 16) = pbvl;
        __syncthreads();

        if (kt + 1 < nk) {
            int k0 = (kt + 1) << 5;
            int gm0 = bm + ra0, gm1 = bm + ra1;
            if (gm0 < M) { pavh0 = *(const uint4*)(Ah + (size_t)gm0 * K + k0 + qa0 * 8);
                           pavl0 = *(const uint4*)(Al + (size_t)gm0 * K + k0 + qa0 * 8); }
            if (gm1 < M) { pavh1 = *(const uint4*)(Ah + (size_t)gm1 * K + k0 + qa1 * 8);
                           pavl1 = *(const uint4*)(Al + (size_t)gm1 * K + k0 + qa1 * 8); }
            pbvh = *(const uint4*)(Bth + (size_t)rb * K + k0 + qb * 8);
            pbvl = *(const uint4*)(Btl + (size_t)rb * K + k0 + qb * 8);
        }

        #pragma unroll
        for (int kk = 0; kk < 32; kk += 16) {
            uint32_t ah[2][4], al[2][4], bhf[4][2], blf[4][2];
            #pragma unroll
            for (int i = 0; i < 2; i++) {
                int r = wm * 32 + i * 16;
                ah[i][0] = lds_u32(sAh, r + g,     kk + t2);
                ah[i][1] = lds_u32(sAh, r + g + 8, kk + t2);
                ah[i][2] = lds_u32(sAh, r + g,     kk + t2 + 8);
                ah[i][3] = lds_u32(sAh, r + g + 8, kk + t2 + 8);
                al[i][0] = lds_u32(sAl, r + g,     kk + t2);
                al[i][1] = lds_u32(sAl, r + g + 8, kk + t2);
                al[i][2] = lds_u32(sAl, r + g,     kk + t2 + 8);
                al[i][3] = lds_u32(sAl, r + g + 8, kk + t2 + 8);
            }
            #pragma unroll
            for (int j = 0; j < 4; j++) {
                int n = wn * 32 + j * 8 + g;
                bhf[j][0] = lds_u32(sBh, n, kk + t2);
                bhf[j][1] = lds_u32(sBh, n, kk + t2 + 8);
                blf[j][0] = lds_u32(sBl, n, kk + t2);
                blf[j][1] = lds_u32(sBl, n, kk + t2 + 8);
            }
            #pragma unroll
            for (int i = 0; i < 2; i++)
                #pragma unroll
                for (int j = 0; j < 4; j++) {
                    mma_bf16(acc[i][j], ah[i], bhf[j]);
                    mma_bf16(acc[i][j], ah[i], blf[j]);
                    mma_bf16(acc[i][j], al[i], bhf[j]);
                }
        }
        __syncthreads();
    }

    #pragma unroll
    for (int i = 0; i < 2; i++) {
        int r0 = bm + wm * 32 + i * 16 + g;
        #pragma unroll
        for (int j = 0; j < 4; j++) {
            int c = nt * 64 + wn * 32 + j * 8 + t2;
            if (r0 < M)
                *(float2*)(C + (size_t)r0 * N + c) = make_float2(acc[i][j][0], acc[i][j][1]);
            if (r0 + 8 < M)
                *(float2*)(C + (size_t)(r0 + 8) * N + c) = make_float2(acc[i][j][2], acc[i][j][3]);
        }
    }
}

// ---------------- fused GAT layer 1 (block/node, warp/head, dual-edge) --------
__global__ void gat1_kernel(const float* __restrict__ att, const float* __restrict__ b1)
{
    int n = blockIdx.x;
    int w = threadIdx.x >> 5, l = threadIdx.x & 31;
    int half = l >> 4, hl = l & 15;
    int c = w * 64 + hl * 4;

    float4 xr = *(const float4*)(g_xr1 + (size_t)n * F1 + c);
    float4 at = *(const float4*)(att + c);

    int r0 = g_rowptr[n], r1 = g_rowptr[n + 1];
    int nIter = (r1 - r0 + 1) >> 1;
    float m = -INFINITY, den = 0.f;
    float4 acc = make_float4(0.f, 0.f, 0.f, 0.f);

    for (int it = 0; it < nIter; it++) {
        int p = r0 + it * 2 + half;
        bool valid = p < r1;
        int pp = valid ? p : (r1 - 1);
        int s = g_esrc[pp];
        float4 xl = *(const float4*)(g_xl1 + (size_t)s * F1 + c);
        float v0 = xl.x + xr.x; v0 = v0 > 0.f ? v0 : 0.2f * v0;
        float v1 = xl.y + xr.y; v1 = v1 > 0.f ? v1 : 0.2f * v1;
        float v2 = xl.z + xr.z; v2 = v2 > 0.f ? v2 : 0.2f * v2;
        float v3 = xl.w + xr.w; v3 = v3 > 0.f ? v3 : 0.2f * v3;
        float sc = v0 * at.x + v1 * at.y + v2 * at.z + v3 * at.w;
        sc += __shfl_xor_sync(0xffffffffu, sc, 1);
        sc += __shfl_xor_sync(0xffffffffu, sc, 2);
        sc += __shfl_xor_sync(0xffffffffu, sc, 4);
        sc += __shfl_xor_sync(0xffffffffu, sc, 8);
        if (valid && sc > m) {
            float r = __expf(m - sc);
            den *= r; acc.x *= r; acc.y *= r; acc.z *= r; acc.w *= r; m = sc;
        }
        float a = valid ? __expf(sc - m) : 0.f;
        den += a;
        acc.x += a * xl.x; acc.y += a * xl.y; acc.z += a * xl.z; acc.w += a * xl.w;
    }

    float mo   = __shfl_xor_sync(0xffffffffu, m, 16);
    float deno = __shfl_xor_sync(0xffffffffu, den, 16);
    float4 ao;
    ao.x = __shfl_xor_sync(0xffffffffu, acc.x, 16);
    ao.y = __shfl_xor_sync(0xffffffffu, acc.y, 16);
    ao.z = __shfl_xor_sync(0xffffffffu, acc.z, 16);
    ao.w = __shfl_xor_sync(0xffffffffu, acc.w, 16);
    float M = fmaxf(m, mo);
    float sA = (m  > -INFINITY) ? __expf(m  - M) : 0.f;
    float sB = (mo > -INFINITY) ? __expf(mo - M) : 0.f;
    den = den * sA + deno * sB;
    acc.x = acc.x * sA + ao.x * sB;
    acc.y = acc.y * sA + ao.y * sB;
    acc.z = acc.z * sA + ao.z * sB;
    acc.w = acc.w * sA + ao.w * sB;

    if (half == 0) {
        float4 bb = *(const float4*)(b1 + c);
        float invd = 1.0f / den;
        float o0 = acc.x * invd + bb.x; o0 = o0 > 0.f ? o0 : __expf(o0) - 1.f;
        float o1 = acc.y * invd + bb.y; o1 = o1 > 0.f ? o1 : __expf(o1) - 1.f;
        float o2 = acc.z * invd + bb.z; o2 = o2 > 0.f ? o2 : __expf(o2) - 1.f;
        float o3 = acc.w * invd + bb.w; o3 = o3 > 0.f ? o3 : __expf(o3) - 1.f;
        __nv_bfloat16 h[4], lo[4];
        split2(o0, &h[0], &lo[0]); split2(o1, &h[1], &lo[1]);
        split2(o2, &h[2], &lo[2]); split2(o3, &h[3], &lo[3]);
        *(uint2*)(g_h1h  + (size_t)n * F1 + c) = *(const uint2*)h;
        *(uint2*)(g_h1lo + (size_t)n * F1 + c) = *(const uint2*)lo;
    }
}

// ---------------- fused GAT layer 2 + linear + elu (dual-edge) ----------------
__global__ void gat2_kernel(const float* __restrict__ att, const float* __restrict__ b2,
                            const float* __restrict__ Wlin, const float* __restrict__ blin,
                            float* __restrict__ out)
{
    __shared__ float sW[64 * 32];
    __shared__ float sb[32];
    __shared__ float sh2[8][64];
    for (int i = threadIdx.x; i < 64 * 32; i += 256) sW[i] = Wlin[i];
    if (threadIdx.x < 32) sb[threadIdx.x] = blin[threadIdx.x];
    __syncthreads();

    int w = threadIdx.x >> 5, l = threadIdx.x & 31;
    int half = l >> 4, hl = l & 15;
    int n = blockIdx.x * 8 + w;
    int c = hl * 4;

    float4 xr = *(const float4*)(g_xr2 + (size_t)n * F2 + c);
    float4 at = *(const float4*)(att + c);

    int r0 = g_rowptr[n], r1 = g_rowptr[n + 1];
    int nIter = (r1 - r0 + 1) >> 1;
    float m = -INFINITY, den = 0.f;
    float4 acc = make_float4(0.f, 0.f, 0.f, 0.f);

    for (int it = 0; it < nIter; it++) {
        int p = r0 + it * 2 + half;
        bool valid = p < r1;
        int pp = valid ? p : (r1 - 1);
        int s = g_esrc[pp];
        float4 xl = *(const float4*)(g_xl2 + (size_t)s * F2 + c);
        float v0 = xl.x + xr.x; v0 = v0 > 0.f ? v0 : 0.2f * v0;
        float v1 = xl.y + xr.y; v1 = v1 > 0.f ? v1 : 0.2f * v1;
        float v2 = xl.z + xr.z; v2 = v2 > 0.f ? v2 : 0.2f * v2;
        float v3 = xl.w + xr.w; v3 = v3 > 0.f ? v3 : 0.2f * v3;
        float sc = v0 * at.x + v1 * at.y + v2 * at.z + v3 * at.w;
        sc += __shfl_xor_sync(0xffffffffu, sc, 1);
        sc += __shfl_xor_sync(0xffffffffu, sc, 2);
        sc += __shfl_xor_sync(0xffffffffu, sc, 4);
        sc += __shfl_xor_sync(0xffffffffu, sc, 8);
        if (valid && sc > m) {
            float r = __expf(m - sc);
            den *= r; acc.x *= r; acc.y *= r; acc.z *= r; acc.w *= r; m = sc;
        }
        float a = valid ? __expf(sc - m) : 0.f;
        den += a;
        acc.x += a * xl.x; acc.y += a * xl.y; acc.z += a * xl.z; acc.w += a * xl.w;
    }

    float mo   = __shfl_xor_sync(0xffffffffu, m, 16);
    float deno = __shfl_xor_sync(0xffffffffu, den, 16);
    float4 ao;
    ao.x = __shfl_xor_sync(0xffffffffu, acc.x, 16);
    ao.y = __shfl_xor_sync(0xffffffffu, acc.y, 16);
    ao.z = __shfl_xor_sync(0xffffffffu, acc.z, 16);
    ao.w = __shfl_xor_sync(0xffffffffu, acc.w, 16);
    float M = fmaxf(m, mo);
    float sA = (m  > -INFINITY) ? __expf(m  - M) : 0.f;
    float sB = (mo > -INFINITY) ? __expf(mo - M) : 0.f;
    den = den * sA + deno * sB;
    acc.x = acc.x * sA + ao.x * sB;
    acc.y = acc.y * sA + ao.y * sB;
    acc.z = acc.z * sA + ao.z * sB;
    acc.w = acc.w * sA + ao.w * sB;

    if (half == 0) {
        float4 bb = *(const float4*)(b2 + c);
        float invd = 1.0f / den;
        float h0 = acc.x * invd + bb.x; h0 = h0 > 0.f ? h0 : __expf(h0) - 1.f;
        float h1 = acc.y * invd + bb.y; h1 = h1 > 0.f ? h1 : __expf(h1) - 1.f;
        float h2 = acc.z * invd + bb.z; h2 = h2 > 0.f ? h2 : __expf(h2) - 1.f;
        float h3 = acc.w * invd + bb.w; h3 = h3 > 0.f ? h3 : __expf(h3) - 1.f;
        sh2[w][c] = h0; sh2[w][c + 1] = h1; sh2[w][c + 2] = h2; sh2[w][c + 3] = h3;
    }
    __syncwarp();

    float o = sb[l];
    #pragma unroll
    for (int k = 0; k < 64; k++) o += sh2[w][k] * sW[k * 32 + l];
    out[(size_t)n * OUTF + l] = o > 0.f ? o : __expf(o) - 1.f;
}

// ---------------- launch ------------------------------------------------------
extern "C" void kernel_launch(void* const* d_in, const int* in_sizes, int n_in,
                              void* d_out, int out_size) {
    const float* x    = (const float*)d_in[0];
    const int*   ei   = (const int*)  d_in[1];
    const float* W1l  = (const float*)d_in[2];
    const float* W1r  = (const float*)d_in[3];
    const float* att1 = (const float*)d_in[4];
    const float* b1   = (const float*)d_in[5];
    const float* W2l  = (const float*)d_in[6];
    const float* W2r  = (const float*)d_in[7];
    const float* att2 = (const float*)d_in[8];
    const float* b2   = (const float*)d_in[9];
    const float* Wlin = (const float*)d_in[10];
    const float* blin = (const float*)d_in[11];
    float* out = (float*)d_out;

    float *p_xl1, *p_xr1, *p_xl2, *p_xr2;
    int* p_deg;
    __nv_bfloat16 *p_xh, *p_xlo, *p_w1h, *p_w1lo, *p_h1h, *p_h1lo, *p_w2h, *p_w2lo;
    cudaGetSymbolAddress((void**)&p_xl1,  g_xl1);
    cudaGetSymbolAddress((void**)&p_xr1,  g_xr1);
    cudaGetSymbolAddress((void**)&p_xl2,  g_xl2);
    cudaGetSymbolAddress((void**)&p_xr2,  g_xr2);
    cudaGetSymbolAddress((void**)&p_deg,  g_deg);
    cudaGetSymbolAddress((void**)&p_xh,   g_xh);
    cudaGetSymbolAddress((void**)&p_xlo,  g_xlo);
    cudaGetSymbolAddress((void**)&p_w1h,  g_w1h);
    cudaGetSymbolAddress((void**)&p_w1lo, g_w1lo);
    cudaGetSymbolAddress((void**)&p_h1h,  g_h1h);
    cudaGetSymbolAddress((void**)&p_h1lo, g_h1lo);
    cudaGetSymbolAddress((void**)&p_w2h,  g_w2h);
    cudaGetSymbolAddress((void**)&p_w2lo, g_w2lo);

    static cudaStream_t s2 = nullptr;
    static cudaEvent_t evFork = nullptr, evJoin = nullptr;
    if (s2 == nullptr) {
        cudaStreamCreateWithFlags(&s2, cudaStreamNonBlocking);
        cudaEventCreateWithFlags(&evFork, cudaEventDisableTiming);
        cudaEventCreateWithFlags(&evJoin, cudaEventDisableTiming);
    }

    cudaEventRecord(evFork, 0);
    cudaStreamWaitEvent(s2, evFork, 0);

    // --- branch A (s2): CSR build ---
    cudaMemsetAsync(p_deg, 0, N_NODES * sizeof(int), s2);
    count_kernel<<<(E_TOT + 255) / 256, 256, 0, s2>>>(ei);
    int nblk = (N_NODES + 1023) / 1024;
    scan1_kernel<<<nblk, 1024, 0, s2>>>();
    scan23_kernel<<<(N_NODES + 255) / 256, 256, 0, s2>>>();
    scatter_kernel<<<(E_TOT + 255) / 256, 256, 0, s2>>>(ei);
    cudaEventRecord(evJoin, s2);

    // --- branch B (main): splits + layer-1 GEMM ---
    split_x_kernel<<<(N_NODES * D_IN + 255) / 256, 256>>>(x);
    split_w_kernel<<<(F1 * D_IN + F2 * F1 + 255) / 256, 256>>>(W1l, W1r, W2l, W2r);
    gemm_mma<<<dim3(16, (N_NODES + 127) / 128), 256>>>(
        p_xh, p_xlo, p_w1h, p_w1lo, p_xl1, p_xr1, N_NODES, F1, D_IN, 8);

    cudaStreamWaitEvent(0, evJoin, 0);
    gat1_kernel<<<N_NODES, 256>>>(att1, b1);

    gemm_mma<<<dim3(2, (N_NODES + 127) / 128), 256>>>(
        p_h1h, p_h1lo, p_w2h, p_w2lo, p_xl2, p_xr2, N_NODES, F2, F1, 1);
    gat2_kernel<<<N_NODES / 8, 256>>>(att2, b2, Wlin, blin, out);
}

// round 13
// speedup vs baseline: 1.8009x; 1.0631x over previous
#include <cuda_runtime.h>
#include <cuda_bf16.h>
#include <math.h>
#include <stdint.h>

#define N_NODES 20000
#define D_IN    128
#define E_RAW   320000
#define E_TOT   (E_RAW + N_NODES)
#define F1      512
#define F2      64
#define OUTF    32

// ---------------- scratch ----------------------------------------------------
__device__ float g_xl1[(size_t)N_NODES * F1];
__device__ float g_xr1[(size_t)N_NODES * F1];
__device__ float g_xl2[(size_t)N_NODES * F2];
__device__ float g_xr2[(size_t)N_NODES * F2];
__device__ int   g_deg[N_NODES];
__device__ int   g_part[N_NODES];
__device__ int   g_bsum[32];
__device__ int   g_rowptr[N_NODES + 1];
__device__ int   g_cursor[N_NODES];
__device__ int   g_esrc[E_TOT];      // CSR edge list, source node id (pre-resolved)
// split-bf16 operands
__device__ __nv_bfloat16 g_xh  [(size_t)N_NODES * D_IN];
__device__ __nv_bfloat16 g_xlo [(size_t)N_NODES * D_IN];
__device__ __nv_bfloat16 g_h1h [(size_t)N_NODES * F1];
__device__ __nv_bfloat16 g_h1lo[(size_t)N_NODES * F1];
__device__ __nv_bfloat16 g_w1h [2 * F1 * D_IN];   // [w][n][k]
__device__ __nv_bfloat16 g_w1lo[2 * F1 * D_IN];
__device__ __nv_bfloat16 g_w2h [2 * F2 * F1];     // [w][n][k]
__device__ __nv_bfloat16 g_w2lo[2 * F2 * F1];

__device__ __forceinline__ int e_dst(const int* ei, int e) {
    return (e < E_RAW) ? ei[E_RAW + e] : (e - E_RAW);
}

// ---------------- CSR build --------------------------------------------------
__global__ void count_kernel(const int* __restrict__ ei) {
    int e = blockIdx.x * blockDim.x + threadIdx.x;
    if (e >= E_TOT) return;
    atomicAdd(&g_deg[e_dst(ei, e)], 1);
}

__global__ void scan1_kernel() {
    __shared__ int sh[1024];
    int t = threadIdx.x;
    int i = blockIdx.x * 1024 + t;
    int v = (i < N_NODES) ? g_deg[i] : 0;
    sh[t] = v;
    __syncthreads();
    #pragma unroll
    for (int off = 1; off < 1024; off <<= 1) {
        int u = (t >= off) ? sh[t - off] : 0;
        __syncthreads();
        sh[t] += u;
        __syncthreads();
    }
    if (i < N_NODES) g_part[i] = sh[t];
    if (t == 1023) g_bsum[blockIdx.x] = sh[t];
}
__global__ void scan23_kernel() {
    int i = blockIdx.x * blockDim.x + threadIdx.x;
    if (i >= N_NODES) return;
    int b = i >> 10;
    int boff = 0;
    for (int j = 0; j < b; j++) boff += g_bsum[j];
    int rp = g_part[i] - g_deg[i] + boff;
    g_rowptr[i] = rp;
    g_cursor[i] = rp;
    if (i == N_NODES - 1) g_rowptr[N_NODES] = g_part[i] + boff;
}

__global__ void scatter_kernel(const int* __restrict__ ei) {
    int e = blockIdx.x * blockDim.x + threadIdx.x;
    if (e >= E_TOT) return;
    int s, d;
    if (e < E_RAW) { s = ei[e]; d = ei[E_RAW + e]; }
    else           { s = e - E_RAW; d = s; }
    int pos = atomicAdd(&g_cursor[d], 1);
    g_esrc[pos] = s;
}

// ---------------- fp32 -> split bf16 (hi + lo) --------------------------------
__device__ __forceinline__ void split2(float v, __nv_bfloat16* ph, __nv_bfloat16* pl) {
    __nv_bfloat16 h = __float2bfloat16(v);
    *ph = h;
    *pl = __float2bfloat16(v - __bfloat162float(h));
}
__global__ void split_x_kernel(const float* __restrict__ x) {
    int i = blockIdx.x * blockDim.x + threadIdx.x;
    if (i >= N_NODES * D_IN) return;
    split2(x[i], &g_xh[i], &g_xlo[i]);
}
__global__ void split_w_kernel(const float* __restrict__ W1l, const float* __restrict__ W1r,
                               const float* __restrict__ W2l, const float* __restrict__ W2r) {
    int i = blockIdx.x * blockDim.x + threadIdx.x;
    if (i < F1 * D_IN) {
        int k = i / F1, n = i % F1;
        split2(W1l[i], &g_w1h[n * D_IN + k], &g_w1lo[n * D_IN + k]);
        split2(W1r[i], &g_w1h[F1 * D_IN + n * D_IN + k], &g_w1lo[F1 * D_IN + n * D_IN + k]);
    } else {
        int j = i - F1 * D_IN;
        if (j >= F2 * F1) return;
        int k = j / F2, n = j % F2;
        split2(W2l[j], &g_w2h[n * F1 + k], &g_w2lo[n * F1 + k]);
        split2(W2r[j], &g_w2h[F2 * F1 + n * F1 + k], &g_w2lo[F2 * F1 + n * F1 + k]);
    }
}

// ---------------- split-bf16 GEMM on mma.sync + ldmatrix frag loads -----------
#define SPAD 40

__device__ __forceinline__ void mma_bf16(float* c, const uint32_t* a, const uint32_t* b) {
    asm volatile(
        "mma.sync.aligned.m16n8k16.row.col.f32.bf16.bf16.f32 "
        "{%0,%1,%2,%3}, {%4,%5,%6,%7}, {%8,%9}, {%0,%1,%2,%3};"
        : "+f"(c[0]), "+f"(c[1]), "+f"(c[2]), "+f"(c[3])
        : "r"(a[0]), "r"(a[1]), "r"(a[2]), "r"(a[3]), "r"(b[0]), "r"(b[1]));
}
__device__ __forceinline__ void ldsm4(uint32_t* r, uint32_t addr) {
    asm volatile("ldmatrix.sync.aligned.m8n8.x4.shared.b16 {%0,%1,%2,%3}, [%4];"
                 : "=r"(r[0]), "=r"(r[1]), "=r"(r[2]), "=r"(r[3]) : "r"(addr));
}

__global__ void __launch_bounds__(256) gemm_mma(
    const __nv_bfloat16* __restrict__ Ah, const __nv_bfloat16* __restrict__ Al,
    const __nv_bfloat16* __restrict__ Bh, const __nv_bfloat16* __restrict__ Bl,
    float* __restrict__ C0, float* __restrict__ C1,
    int M, int N, int K, int ntPerW)
{
    __shared__ __nv_bfloat16 sAh[128 * SPAD], sAl[128 * SPAD];
    __shared__ __nv_bfloat16 sBh[64 * SPAD],  sBl[64 * SPAD];

    int tid = threadIdx.x;
    int wid = tid >> 5, lane = tid & 31;
    int w  = blockIdx.x / ntPerW;
    int nt = blockIdx.x % ntPerW;
    int bm = blockIdx.y * 128;

    const __nv_bfloat16* Bth = Bh + (size_t)w * N * K + (size_t)(nt * 64) * K;
    const __nv_bfloat16* Btl = Bl + (size_t)w * N * K + (size_t)(nt * 64) * K;
    float* C = w ? C1 : C0;

    int wm = wid & 3, wn = wid >> 2;
    int g = lane >> 2, t2 = (lane & 3) * 2;

    // ldmatrix lane address offsets (verified mapping from R9)
    uint32_t sAh_b = (uint32_t)__cvta_generic_to_shared(sAh);
    uint32_t sAl_b = (uint32_t)__cvta_generic_to_shared(sAl);
    uint32_t sBh_b = (uint32_t)__cvta_generic_to_shared(sBh);
    uint32_t sBl_b = (uint32_t)__cvta_generic_to_shared(sBl);
    int aRow = wm * 32 + (lane & 7) + ((lane >> 3) & 1) * 8;
    int aCol = (lane >> 4) * 8;
    uint32_t aOff0 = (uint32_t)(aRow * (SPAD * 2) + aCol * 2);
    uint32_t aOff1 = aOff0 + 16 * (SPAD * 2);
    int bRow = wn * 32 + (lane & 7) + (lane >> 4) * 8;
    int bCol = ((lane >> 3) & 1) * 8;
    uint32_t bOff0 = (uint32_t)(bRow * (SPAD * 2) + bCol * 2);
    uint32_t bOff1 = bOff0 + 16 * (SPAD * 2);

    int ra0 = tid >> 2, qa0 = tid & 3;
    int ra1 = (tid + 256) >> 2, qa1 = (tid + 256) & 3;
    int rb = tid >> 2, qb = tid & 3;

    float acc[2][4][4];
    #pragma unroll
    for (int i = 0; i < 2; i++)
        #pragma unroll
        for (int j = 0; j < 4; j++)
            #pragma unroll
            for (int q = 0; q < 4; q++) acc[i][j][q] = 0.f;

    int nk = K >> 5;
    uint4 pavh0, pavl0, pavh1, pavl1, pbvh, pbvl;
    {
        int gm0 = bm + ra0, gm1 = bm + ra1;
        pavh0 = pavl0 = make_uint4(0,0,0,0);
        pavh1 = pavl1 = make_uint4(0,0,0,0);
        if (gm0 < M) { pavh0 = *(const uint4*)(Ah + (size_t)gm0 * K + qa0 * 8);
                       pavl0 = *(const uint4*)(Al + (size_t)gm0 * K + qa0 * 8); }
        if (gm1 < M) { pavh1 = *(const uint4*)(Ah + (size_t)gm1 * K + qa1 * 8);
                       pavl1 = *(const uint4*)(Al + (size_t)gm1 * K + qa1 * 8); }
        pbvh = *(const uint4*)(Bth + (size_t)rb * K + qb * 8);
        pbvl = *(const uint4*)(Btl + (size_t)rb * K + qb * 8);
    }

    for (int kt = 0; kt < nk; kt++) {
        *(uint4*)((char*)sAh + ra0 * (SPAD * 2) + qa0 * 16) = pavh0;
        *(uint4*)((char*)sAl + ra0 * (SPAD * 2) + qa0 * 16) = pavl0;
        *(uint4*)((char*)sAh + ra1 * (SPAD * 2) + qa1 * 16) = pavh1;
        *(uint4*)((char*)sAl + ra1 * (SPAD * 2) + qa1 * 16) = pavl1;
        *(uint4*)((char*)sBh + rb * (SPAD * 2) + qb * 16) = pbvh;
        *(uint4*)((char*)sBl + rb * (SPAD * 2) + qb * 16) = pbvl;
        __syncthreads();

        if (kt + 1 < nk) {
            int k0 = (kt + 1) << 5;
            int gm0 = bm + ra0, gm1 = bm + ra1;
            if (gm0 < M) { pavh0 = *(const uint4*)(Ah + (size_t)gm0 * K + k0 + qa0 * 8);
                           pavl0 = *(const uint4*)(Al + (size_t)gm0 * K + k0 + qa0 * 8); }
            if (gm1 < M) { pavh1 = *(const uint4*)(Ah + (size_t)gm1 * K + k0 + qa1 * 8);
                           pavl1 = *(const uint4*)(Al + (size_t)gm1 * K + k0 + qa1 * 8); }
            pbvh = *(const uint4*)(Bth + (size_t)rb * K + k0 + qb * 8);
            pbvl = *(const uint4*)(Btl + (size_t)rb * K + k0 + qb * 8);
        }

        #pragma unroll
        for (int kk = 0; kk < 32; kk += 16) {
            uint32_t kb = (uint32_t)(kk * 2);
            uint32_t ah[2][4], al[2][4], bh[4][2], bl[4][2], t[4];
            ldsm4(ah[0], sAh_b + aOff0 + kb);
            ldsm4(ah[1], sAh_b + aOff1 + kb);
            ldsm4(al[0], sAl_b + aOff0 + kb);
            ldsm4(al[1], sAl_b + aOff1 + kb);
            ldsm4(t, sBh_b + bOff0 + kb);
            bh[0][0]=t[0]; bh[0][1]=t[1]; bh[1][0]=t[2]; bh[1][1]=t[3];
            ldsm4(t, sBh_b + bOff1 + kb);
            bh[2][0]=t[0]; bh[2][1]=t[1]; bh[3][0]=t[2]; bh[3][1]=t[3];
            ldsm4(t, sBl_b + bOff0 + kb);
            bl[0][0]=t[0]; bl[0][1]=t[1]; bl[1][0]=t[2]; bl[1][1]=t[3];
            ldsm4(t, sBl_b + bOff1 + kb);
            bl[2][0]=t[0]; bl[2][1]=t[1]; bl[3][0]=t[2]; bl[3][1]=t[3];
            #pragma unroll
            for (int i = 0; i < 2; i++)
                #pragma unroll
                for (int j = 0; j < 4; j++) {
                    mma_bf16(acc[i][j], ah[i], bh[j]);
                    mma_bf16(acc[i][j], ah[i], bl[j]);
                    mma_bf16(acc[i][j], al[i], bh[j]);
                }
        }
        __syncthreads();
    }

    #pragma unroll
    for (int i = 0; i < 2; i++) {
        int r0 = bm + wm * 32 + i * 16 + g;
        #pragma unroll
        for (int j = 0; j < 4; j++) {
            int c = nt * 64 + wn * 32 + j * 8 + t2;
            if (r0 < M)
                *(float2*)(C + (size_t)r0 * N + c) = make_float2(acc[i][j][0], acc[i][j][1]);
            if (r0 + 8 < M)
                *(float2*)(C + (size_t)(r0 + 8) * N + c) = make_float2(acc[i][j][2], acc[i][j][3]);
        }
    }
}

// ---------------- fused GAT layer 1 (block/node, warp/head, dual-edge) --------
__global__ void gat1_kernel(const float* __restrict__ att, const float* __restrict__ b1)
{
    int n = blockIdx.x;
    int w = threadIdx.x >> 5, l = threadIdx.x & 31;
    int half = l >> 4, hl = l & 15;
    int c = w * 64 + hl * 4;

    float4 xr = *(const float4*)(g_xr1 + (size_t)n * F1 + c);
    float4 at = *(const float4*)(att + c);

    int r0 = g_rowptr[n], r1 = g_rowptr[n + 1];
    int nIter = (r1 - r0 + 1) >> 1;
    float m = -INFINITY, den = 0.f;
    float4 acc = make_float4(0.f, 0.f, 0.f, 0.f);

    for (int it = 0; it < nIter; it++) {
        int p = r0 + it * 2 + half;
        bool valid = p < r1;
        int pp = valid ? p : (r1 - 1);
        int s = g_esrc[pp];
        float4 xl = *(const float4*)(g_xl1 + (size_t)s * F1 + c);
        float v0 = xl.x + xr.x; v0 = v0 > 0.f ? v0 : 0.2f * v0;
        float v1 = xl.y + xr.y; v1 = v1 > 0.f ? v1 : 0.2f * v1;
        float v2 = xl.z + xr.z; v2 = v2 > 0.f ? v2 : 0.2f * v2;
        float v3 = xl.w + xr.w; v3 = v3 > 0.f ? v3 : 0.2f * v3;
        float sc = v0 * at.x + v1 * at.y + v2 * at.z + v3 * at.w;
        sc += __shfl_xor_sync(0xffffffffu, sc, 1);
        sc += __shfl_xor_sync(0xffffffffu, sc, 2);
        sc += __shfl_xor_sync(0xffffffffu, sc, 4);
        sc += __shfl_xor_sync(0xffffffffu, sc, 8);
        if (valid && sc > m) {
            float r = __expf(m - sc);
            den *= r; acc.x *= r; acc.y *= r; acc.z *= r; acc.w *= r; m = sc;
        }
        float a = valid ? __expf(sc - m) : 0.f;
        den += a;
        acc.x += a * xl.x; acc.y += a * xl.y; acc.z += a * xl.z; acc.w += a * xl.w;
    }

    float mo   = __shfl_xor_sync(0xffffffffu, m, 16);
    float deno = __shfl_xor_sync(0xffffffffu, den, 16);
    float4 ao;
    ao.x = __shfl_xor_sync(0xffffffffu, acc.x, 16);
    ao.y = __shfl_xor_sync(0xffffffffu, acc.y, 16);
    ao.z = __shfl_xor_sync(0xffffffffu, acc.z, 16);
    ao.w = __shfl_xor_sync(0xffffffffu, acc.w, 16);
    float M = fmaxf(m, mo);
    float sA = (m  > -INFINITY) ? __expf(m  - M) : 0.f;
    float sB = (mo > -INFINITY) ? __expf(mo - M) : 0.f;
    den = den * sA + deno * sB;
    acc.x = acc.x * sA + ao.x * sB;
    acc.y = acc.y * sA + ao.y * sB;
    acc.z = acc.z * sA + ao.z * sB;
    acc.w = acc.w * sA + ao.w * sB;

    if (half == 0) {
        float4 bb = *(const float4*)(b1 + c);
        float invd = 1.0f / den;
        float o0 = acc.x * invd + bb.x; o0 = o0 > 0.f ? o0 : __expf(o0) - 1.f;
        float o1 = acc.y * invd + bb.y; o1 = o1 > 0.f ? o1 : __expf(o1) - 1.f;
        float o2 = acc.z * invd + bb.z; o2 = o2 > 0.f ? o2 : __expf(o2) - 1.f;
        float o3 = acc.w * invd + bb.w; o3 = o3 > 0.f ? o3 : __expf(o3) - 1.f;
        __nv_bfloat16 h[4], lo[4];
        split2(o0, &h[0], &lo[0]); split2(o1, &h[1], &lo[1]);
        split2(o2, &h[2], &lo[2]); split2(o3, &h[3], &lo[3]);
        *(uint2*)(g_h1h  + (size_t)n * F1 + c) = *(const uint2*)h;
        *(uint2*)(g_h1lo + (size_t)n * F1 + c) = *(const uint2*)lo;
    }
}

// ---------------- fused GAT layer 2 + linear + elu (dual-edge) ----------------
__global__ void gat2_kernel(const float* __restrict__ att, const float* __restrict__ b2,
                            const float* __restrict__ Wlin, const float* __restrict__ blin,
                            float* __restrict__ out)
{
    __shared__ float sW[64 * 32];
    __shared__ float sb[32];
    __shared__ float sh2[8][64];
    for (int i = threadIdx.x; i < 64 * 32; i += 256) sW[i] = Wlin[i];
    if (threadIdx.x < 32) sb[threadIdx.x] = blin[threadIdx.x];
    __syncthreads();

    int w = threadIdx.x >> 5, l = threadIdx.x & 31;
    int half = l >> 4, hl = l & 15;
    int n = blockIdx.x * 8 + w;
    int c = hl * 4;

    float4 xr = *(const float4*)(g_xr2 + (size_t)n * F2 + c);
    float4 at = *(const float4*)(att + c);

    int r0 = g_rowptr[n], r1 = g_rowptr[n + 1];
    int nIter = (r1 - r0 + 1) >> 1;
    float m = -INFINITY, den = 0.f;
    float4 acc = make_float4(0.f, 0.f, 0.f, 0.f);

    for (int it = 0; it < nIter; it++) {
        int p = r0 + it * 2 + half;
        bool valid = p < r1;
        int pp = valid ? p : (r1 - 1);
        int s = g_esrc[pp];
        float4 xl = *(const float4*)(g_xl2 + (size_t)s * F2 + c);
        float v0 = xl.x + xr.x; v0 = v0 > 0.f ? v0 : 0.2f * v0;
        float v1 = xl.y + xr.y; v1 = v1 > 0.f ? v1 : 0.2f * v1;
        float v2 = xl.z + xr.z; v2 = v2 > 0.f ? v2 : 0.2f * v2;
        float v3 = xl.w + xr.w; v3 = v3 > 0.f ? v3 : 0.2f * v3;
        float sc = v0 * at.x + v1 * at.y + v2 * at.z + v3 * at.w;
        sc += __shfl_xor_sync(0xffffffffu, sc, 1);
        sc += __shfl_xor_sync(0xffffffffu, sc, 2);
        sc += __shfl_xor_sync(0xffffffffu, sc, 4);
        sc += __shfl_xor_sync(0xffffffffu, sc, 8);
        if (valid && sc > m) {
            float r = __expf(m - sc);
            den *= r; acc.x *= r; acc.y *= r; acc.z *= r; acc.w *= r; m = sc;
        }
        float a = valid ? __expf(sc - m) : 0.f;
        den += a;
        acc.x += a * xl.x; acc.y += a * xl.y; acc.z += a * xl.z; acc.w += a * xl.w;
    }

    float mo   = __shfl_xor_sync(0xffffffffu, m, 16);
    float deno = __shfl_xor_sync(0xffffffffu, den, 16);
    float4 ao;
    ao.x = __shfl_xor_sync(0xffffffffu, acc.x, 16);
    ao.y = __shfl_xor_sync(0xffffffffu, acc.y, 16);
    ao.z = __shfl_xor_sync(0xffffffffu, acc.z, 16);
    ao.w = __shfl_xor_sync(0xffffffffu, acc.w, 16);
    float M = fmaxf(m, mo);
    float sA = (m  > -INFINITY) ? __expf(m  - M) : 0.f;
    float sB = (mo > -INFINITY) ? __expf(mo - M) : 0.f;
    den = den * sA + deno * sB;
    acc.x = acc.x * sA + ao.x * sB;
    acc.y = acc.y * sA + ao.y * sB;
    acc.z = acc.z * sA + ao.z * sB;
    acc.w = acc.w * sA + ao.w * sB;

    if (half == 0) {
        float4 bb = *(const float4*)(b2 + c);
        float invd = 1.0f / den;
        float h0 = acc.x * invd + bb.x; h0 = h0 > 0.f ? h0 : __expf(h0) - 1.f;
        float h1 = acc.y * invd + bb.y; h1 = h1 > 0.f ? h1 : __expf(h1) - 1.f;
        float h2 = acc.z * invd + bb.z; h2 = h2 > 0.f ? h2 : __expf(h2) - 1.f;
        float h3 = acc.w * invd + bb.w; h3 = h3 > 0.f ? h3 : __expf(h3) - 1.f;
        sh2[w][c] = h0; sh2[w][c + 1] = h1; sh2[w][c + 2] = h2; sh2[w][c + 3] = h3;
    }
    __syncwarp();

    float o = sb[l];
    #pragma unroll
    for (int k = 0; k < 64; k++) o += sh2[w][k] * sW[k * 32 + l];
    out[(size_t)n * OUTF + l] = o > 0.f ? o : __expf(o) - 1.f;
}

// ---------------- launch ------------------------------------------------------
extern "C" void kernel_launch(void* const* d_in, const int* in_sizes, int n_in,
                              void* d_out, int out_size) {
    const float* x    = (const float*)d_in[0];
    const int*   ei   = (const int*)  d_in[1];
    const float* W1l  = (const float*)d_in[2];
    const float* W1r  = (const float*)d_in[3];
    const float* att1 = (const float*)d_in[4];
    const float* b1   = (const float*)d_in[5];
    const float* W2l  = (const float*)d_in[6];
    const float* W2r  = (const float*)d_in[7];
    const float* att2 = (const float*)d_in[8];
    const float* b2   = (const float*)d_in[9];
    const float* Wlin = (const float*)d_in[10];
    const float* blin = (const float*)d_in[11];
    float* out = (float*)d_out;

    float *p_xl1, *p_xr1, *p_xl2, *p_xr2;
    int* p_deg;
    __nv_bfloat16 *p_xh, *p_xlo, *p_w1h, *p_w1lo, *p_h1h, *p_h1lo, *p_w2h, *p_w2lo;
    cudaGetSymbolAddress((void**)&p_xl1,  g_xl1);
    cudaGetSymbolAddress((void**)&p_xr1,  g_xr1);
    cudaGetSymbolAddress((void**)&p_xl2,  g_xl2);
    cudaGetSymbolAddress((void**)&p_xr2,  g_xr2);
    cudaGetSymbolAddress((void**)&p_deg,  g_deg);
    cudaGetSymbolAddress((void**)&p_xh,   g_xh);
    cudaGetSymbolAddress((void**)&p_xlo,  g_xlo);
    cudaGetSymbolAddress((void**)&p_w1h,  g_w1h);
    cudaGetSymbolAddress((void**)&p_w1lo, g_w1lo);
    cudaGetSymbolAddress((void**)&p_h1h,  g_h1h);
    cudaGetSymbolAddress((void**)&p_h1lo, g_h1lo);
    cudaGetSymbolAddress((void**)&p_w2h,  g_w2h);
    cudaGetSymbolAddress((void**)&p_w2lo, g_w2lo);

    static cudaStream_t s2 = nullptr;
    static cudaEvent_t evFork = nullptr, evJoin = nullptr;
    if (s2 == nullptr) {
        cudaStreamCreateWithFlags(&s2, cudaStreamNonBlocking);
        cudaEventCreateWithFlags(&evFork, cudaEventDisableTiming);
        cudaEventCreateWithFlags(&evJoin, cudaEventDisableTiming);
    }

    cudaEventRecord(evFork, 0);
    cudaStreamWaitEvent(s2, evFork, 0);

    // --- branch A (s2): CSR build ---
    cudaMemsetAsync(p_deg, 0, N_NODES * sizeof(int), s2);
    count_kernel<<<(E_TOT + 255) / 256, 256, 0, s2>>>(ei);
    int nblk = (N_NODES + 1023) / 1024;
    scan1_kernel<<<nblk, 1024, 0, s2>>>();
    scan23_kernel<<<(N_NODES + 255) / 256, 256, 0, s2>>>();
    scatter_kernel<<<(E_TOT + 255) / 256, 256, 0, s2>>>(ei);
    cudaEventRecord(evJoin, s2);

    // --- branch B (main): splits + layer-1 GEMM ---
    split_x_kernel<<<(N_NODES * D_IN + 255) / 256, 256>>>(x);
    split_w_kernel<<<(F1 * D_IN + F2 * F1 + 255) / 256, 256>>>(W1l, W1r, W2l, W2r);
    gemm_mma<<<dim3(16, (N_NODES + 127) / 128), 256>>>(
        p_xh, p_xlo, p_w1h, p_w1lo, p_xl1, p_xr1, N_NODES, F1, D_IN, 8);

    cudaStreamWaitEvent(0, evJoin, 0);
    gat1_kernel<<<N_NODES, 256>>>(att1, b1);

    gemm_mma<<<dim3(2, (N_NODES + 127) / 128), 256>>>(
        p_h1h, p_h1lo, p_w2h, p_w2lo, p_xl2, p_xr2, N_NODES, F2, F1, 1);
    gat2_kernel<<<N_NODES / 8, 256>>>(att2, b2, Wlin, blin, out);
}